// round 12
// baseline (speedup 1.0000x reference)
#include <cuda_runtime.h>
#include <cuda_bf16.h>
#include <cstdint>
#include <math.h>

// Problem constants
#define NG      64          // num graphs
#define NN      512         // nodes per graph
#define GN      32768       // NG*NN
#define D_IN    128
#define E       256
#define NL      4
#define DFF     2048
#define NE_EDGE 524288
#define KSEL    128
#define NH      8
#define HD      32

#define OFF_SAMP (NE_EDGE)
#define OFF_PF   (NE_EDGE + NG * KSEL)

// ---------------- scratch (static device globals; no cudaMalloc allowed) ---
__device__ float g_h[(size_t)GN * E];       // 32 MB  hidden state
__device__ float g_qkv[(size_t)GN * 3 * E]; // 96 MB
__device__ float g_attn[(size_t)GN * E];    // 32 MB  attn output / ff2 output
__device__ float g_ff[(size_t)GN * DFF];    // 256 MB out-proj result then ff1 act
__device__ float g_probs[GN];
__device__ float g_pf[GN];

// ---------------- tf32 helpers ---------------------------------------------
__device__ __forceinline__ float tf32_rna(float x) {
    uint32_t r;
    asm("cvt.rna.tf32.f32 %0, %1;" : "=r"(r) : "f"(x));
    return __uint_as_float(r);
}

// mma.sync m16n8k8 tf32 (baseline sm_80+ PTX — works on plain sm_103 target)
__device__ __forceinline__ void mma_tf32(float* d, const uint32_t* a, const uint32_t* b) {
    asm volatile(
        "mma.sync.aligned.m16n8k8.row.col.f32.tf32.tf32.f32 "
        "{%0,%1,%2,%3}, {%4,%5,%6,%7}, {%8,%9}, {%0,%1,%2,%3};"
        : "+f"(d[0]), "+f"(d[1]), "+f"(d[2]), "+f"(d[3])
        : "r"(a[0]), "r"(a[1]), "r"(a[2]), "r"(a[3]), "r"(b[0]), "r"(b[1]));
}

__device__ __forceinline__ void cp_async16(uint32_t smem_addr, const void* gptr) {
    asm volatile("cp.async.cg.shared.global [%0], [%1], 16;"
                 :: "r"(smem_addr), "l"(gptr));
}
__device__ __forceinline__ void cp_commit() {
    asm volatile("cp.async.commit_group;");
}

// ---------------- tf32x3 tensor-core GEMM, cp.async 2-stage ----------------
// C[M,N] = A[M,K] @ B[N,K]^T + bias, optional relu.
// Block tile 128x64, BK=32, 256 threads = 8 warps (4x2), warp tile 32x32.
// Smem holds RAW fp32 tiles (single copy). tf32 hi/lo split happens in
// registers at fragment-load time. cp.async overlaps the next chunk's
// global loads with the current chunk's mma work. 3 CTAs/SM (24 warps)
// to cover LDS->cvt->mma latency chains.
#define BM   128
#define BN   64
#define BK   32
#define PAD_ROW 36                         // floats per smem row (32 + 4 pad)
#define ST_A  0
#define ST_B  (BM * PAD_ROW)               // 4608
#define STAGE_F (BM * PAD_ROW + BN * PAD_ROW)   // 6912 floats
#define GEMM_SMEM (2 * STAGE_F * 4)        // 55296 B

__global__ void __launch_bounds__(256, 3)
gemm_mma(const float* __restrict__ A, const float* __restrict__ B,
         const float* __restrict__ bias, float* __restrict__ C,
         int K, int N, int relu)
{
    extern __shared__ float sm[];
    const uint32_t smb = (uint32_t)__cvta_generic_to_shared(sm);

    const int tid  = threadIdx.x;
    const int warp = tid >> 5;
    const int lane = tid & 31;
    const int wm   = warp >> 1;            // 0..3  (m direction, 32 rows each)
    const int wn   = warp & 1;             // 0..1  (n direction, 32 cols each)
    const int gid  = lane >> 2;            // 0..7
    const int qid  = lane & 3;             // 0..3
    const int m0   = blockIdx.y * BM;
    const int n0   = blockIdx.x * BN;

    // cp.async indices: A 4 float4/thread, B 2 float4/thread per chunk
    const int lr = tid >> 3;               // 0..31
    const int lc = (tid & 7) * 4;          // 0,4,...,28
    const int NC = K >> 5;

    float acc[2][4][4];
#pragma unroll
    for (int i = 0; i < 2; i++)
#pragma unroll
        for (int j = 0; j < 4; j++)
#pragma unroll
            for (int t = 0; t < 4; t++) acc[i][j][t] = 0.f;

    // stage loader: chunk c -> stage s
    auto load_stage = [&](int c, int s) {
        const float* Ab = A + (size_t)m0 * K + c * BK;
        const float* Bb = B + (size_t)n0 * K + c * BK;
        uint32_t st = smb + (uint32_t)(s * STAGE_F * 4);
#pragma unroll
        for (int i = 0; i < 4; i++) {
            int r = lr + 32 * i;           // 0..127
            cp_async16(st + (uint32_t)((ST_A + r * PAD_ROW + lc) * 4),
                       Ab + (size_t)r * K + lc);
        }
#pragma unroll
        for (int i = 0; i < 2; i++) {
            int r = lr + 32 * i;           // 0..63
            cp_async16(st + (uint32_t)((ST_B + r * PAD_ROW + lc) * 4),
                       Bb + (size_t)r * K + lc);
        }
        cp_commit();
    };

    // prologue: stages 0 and 1 in flight
    load_stage(0, 0);
    if (NC > 1) load_stage(1, 1);

    for (int c = 0; c < NC; c++) {
        // wait until chunk c's group has landed (allow c+1 outstanding)
        if (c + 1 < NC) asm volatile("cp.async.wait_group 1;" ::: "memory");
        else            asm volatile("cp.async.wait_group 0;" ::: "memory");
        __syncthreads();

        const float* st  = sm + (c & 1) * STAGE_F;
        const float* As  = st + ST_A;
        const float* Bs  = st + ST_B;

#pragma unroll
        for (int kk = 0; kk < 4; kk++) {
            const int kb = kk * 8;
            uint32_t a_hi[2][4], a_lo[2][4];
#pragma unroll
            for (int tm = 0; tm < 2; tm++) {
                int r = wm * 32 + tm * 16 + gid;
                float v0 = As[r * PAD_ROW + kb + qid];
                float v1 = As[(r + 8) * PAD_ROW + kb + qid];
                float v2 = As[r * PAD_ROW + kb + qid + 4];
                float v3 = As[(r + 8) * PAD_ROW + kb + qid + 4];
                float h0 = tf32_rna(v0), h1 = tf32_rna(v1);
                float h2 = tf32_rna(v2), h3 = tf32_rna(v3);
                a_hi[tm][0] = __float_as_uint(h0); a_lo[tm][0] = __float_as_uint(v0 - h0);
                a_hi[tm][1] = __float_as_uint(h1); a_lo[tm][1] = __float_as_uint(v1 - h1);
                a_hi[tm][2] = __float_as_uint(h2); a_lo[tm][2] = __float_as_uint(v2 - h2);
                a_hi[tm][3] = __float_as_uint(h3); a_lo[tm][3] = __float_as_uint(v3 - h3);
            }
            uint32_t b_hi[4][2], b_lo[4][2];
#pragma unroll
            for (int tn = 0; tn < 4; tn++) {
                int cc = wn * 32 + tn * 8 + gid;
                float v0 = Bs[cc * PAD_ROW + kb + qid];
                float v1 = Bs[cc * PAD_ROW + kb + qid + 4];
                float h0 = tf32_rna(v0), h1 = tf32_rna(v1);
                b_hi[tn][0] = __float_as_uint(h0); b_lo[tn][0] = __float_as_uint(v0 - h0);
                b_hi[tn][1] = __float_as_uint(h1); b_lo[tn][1] = __float_as_uint(v1 - h1);
            }
#pragma unroll
            for (int tm = 0; tm < 2; tm++)
#pragma unroll
                for (int tn = 0; tn < 4; tn++) {
                    mma_tf32(acc[tm][tn], a_hi[tm], b_hi[tn]);
                    mma_tf32(acc[tm][tn], a_hi[tm], b_lo[tn]);
                    mma_tf32(acc[tm][tn], a_lo[tm], b_hi[tn]);
                }
        }

        // refill the stage we just consumed with chunk c+2
        if (c + 2 < NC) {
            __syncthreads();               // all warps done reading stage c&1
            load_stage(c + 2, c & 1);
        }
    }

    // ---- epilogue: bias (+relu), write fp32 ----
#pragma unroll
    for (int tm = 0; tm < 2; tm++) {
#pragma unroll
        for (int tn = 0; tn < 4; tn++) {
            const float* d = acc[tm][tn];
            int row = m0 + wm * 32 + tm * 16 + gid;
            int col = n0 + wn * 32 + tn * 8 + 2 * qid;
            float bx = bias[col], by = bias[col + 1];
            float2 v0 = make_float2(d[0] + bx, d[1] + by);
            float2 v1 = make_float2(d[2] + bx, d[3] + by);
            if (relu) {
                v0.x = fmaxf(v0.x, 0.f); v0.y = fmaxf(v0.y, 0.f);
                v1.x = fmaxf(v1.x, 0.f); v1.y = fmaxf(v1.y, 0.f);
            }
            *(float2*)(C + (size_t)row * N + col) = v0;
            *(float2*)(C + (size_t)(row + 8) * N + col) = v1;
        }
    }
}

// ---------------- flash-style attention (fp32, proven version) -------------
__global__ void attn_kernel(const float* __restrict__ qkv, float* __restrict__ out)
{
    __shared__ float Ks[64][32];
    __shared__ float Vs[64][32];

    const int g  = blockIdx.x >> 3;
    const int h  = blockIdx.x & 7;
    const int tid = threadIdx.x;
    const int qi = blockIdx.y * 128 + tid;       // 0..511
    const int hc = h * HD;
    const float* base = qkv + (size_t)g * NN * (3 * E);

    float q[HD];
#pragma unroll
    for (int d = 0; d < HD; d++) q[d] = base[(size_t)qi * (3 * E) + hc + d];

    float acc[HD];
#pragma unroll
    for (int d = 0; d < HD; d++) acc[d] = 0.f;
    float mval = -1e30f, l = 0.f;
    const float scale = 0.17677669529663687f;    // 1/sqrt(32)

#pragma unroll 1
    for (int kt = 0; kt < NN; kt += 64) {
        const int row  = tid >> 1;
        const int half = (tid & 1) * 16;
        const float* kp = base + (size_t)(kt + row) * (3 * E) + E + hc + half;
        const float* vp = base + (size_t)(kt + row) * (3 * E) + 2 * E + hc + half;
#pragma unroll
        for (int c = 0; c < 16; c += 4) {
            *(float4*)&Ks[row][half + c] = *(const float4*)(kp + c);
            *(float4*)&Vs[row][half + c] = *(const float4*)(vp + c);
        }
        __syncthreads();

#pragma unroll 1
        for (int jc = 0; jc < 64; jc += 16) {
            float s[16];
            float cmax = -1e30f;
#pragma unroll
            for (int j = 0; j < 16; j++) {
                float sv = 0.f;
#pragma unroll
                for (int d = 0; d < HD; d++) sv = fmaf(q[d], Ks[jc + j][d], sv);
                sv *= scale;
                s[j] = sv;
                cmax = fmaxf(cmax, sv);
            }
            float mnew = fmaxf(mval, cmax);
            float corr = __expf(mval - mnew);
            l *= corr;
#pragma unroll
            for (int d = 0; d < HD; d++) acc[d] *= corr;
#pragma unroll
            for (int j = 0; j < 16; j++) {
                float p = __expf(s[j] - mnew);
                l += p;
#pragma unroll
                for (int d = 0; d < HD; d++)
                    acc[d] = fmaf(p, Vs[jc + j][d], acc[d]);
            }
            mval = mnew;
        }
        __syncthreads();
    }

    float inv = 1.f / l;
    float* op = out + (size_t)(g * NN + qi) * E + hc;
#pragma unroll
    for (int d = 0; d < HD; d++) op[d] = acc[d] * inv;
}

// ---------------- fused residual + LayerNorm (two-pass, fp32) --------------
__global__ void ln_kernel(float* __restrict__ h, const float* __restrict__ add,
                          const float* __restrict__ w, const float* __restrict__ b)
{
    __shared__ float red[256];
    const int r = blockIdx.x;
    const int t = threadIdx.x;
    const size_t off = (size_t)r * E + t;
    float x = h[off] + add[off];

    red[t] = x;
    __syncthreads();
#pragma unroll
    for (int s = 128; s > 0; s >>= 1) {
        if (t < s) red[t] += red[t + s];
        __syncthreads();
    }
    float mu = red[0] * (1.f / E);
    __syncthreads();

    float d = x - mu;
    red[t] = d * d;
    __syncthreads();
#pragma unroll
    for (int s = 128; s > 0; s >>= 1) {
        if (t < s) red[t] += red[t + s];
        __syncthreads();
    }
    float var = red[0] * (1.f / E);
    float y = d * rsqrtf(var + 1e-5f) * w[t] + b[t];
    h[off] = y;
}

// ---------------- score + sigmoid (warp per row) ---------------------------
__global__ void score_kernel(const float* __restrict__ h, const float* __restrict__ sw,
                             const float* __restrict__ sb, float* __restrict__ probs)
{
    const int warp = (blockIdx.x * blockDim.x + threadIdx.x) >> 5;
    const int lane = threadIdx.x & 31;
    if (warp >= GN) return;
    const float* hp = h + (size_t)warp * E;
    float s = 0.f;
#pragma unroll
    for (int k = 0; k < 8; k++) s = fmaf(hp[lane + k * 32], sw[lane + k * 32], s);
#pragma unroll
    for (int o = 16; o; o >>= 1) s += __shfl_xor_sync(0xffffffff, s, o);
    if (lane == 0) {
        s += sb[0];
        probs[warp] = 1.f / (1.f + expf(-s));
    }
}

// ---------------- per-graph top-k (k=128 of n=512) -------------------------
__global__ void topk_kernel(const float* __restrict__ probs,
                            float* __restrict__ out, float* __restrict__ pf_buf)
{
    __shared__ unsigned long long keys[NN];
    __shared__ int sidx[KSEL];
    __shared__ int flags[NN];

    const int g = blockIdx.x;
    const int t = threadIdx.x;
    const float p = probs[g * NN + t];

    unsigned int fb = __float_as_uint(p);
    keys[t] = ((unsigned long long)fb << 32) | (unsigned)(NN - 1 - t);
    __syncthreads();

    for (int k = 2; k <= NN; k <<= 1) {
        for (int j = k >> 1; j > 0; j >>= 1) {
            int ixj = t ^ j;
            if (ixj > t) {
                unsigned long long a = keys[t], b = keys[ixj];
                bool up = ((t & k) == 0);
                if (up ? (a < b) : (a > b)) { keys[t] = b; keys[ixj] = a; }
            }
            __syncthreads();
        }
    }

    if (t < KSEL) sidx[t] = NN - 1 - (int)(unsigned)(keys[t] & 0xFFFFFFFFu);
    __syncthreads();

    for (int k = 2; k <= KSEL; k <<= 1) {
        for (int j = k >> 1; j > 0; j >>= 1) {
            int ixj = t ^ j;
            if (t < KSEL && ixj > t && ixj < KSEL) {
                int a = sidx[t], b = sidx[ixj];
                bool up = ((t & k) == 0);
                if (up ? (a > b) : (a < b)) { sidx[t] = b; sidx[ixj] = a; }
            }
            __syncthreads();
        }
    }

    flags[t] = 0;
    __syncthreads();
    if (t < KSEL) flags[sidx[t]] = 1;
    __syncthreads();

    if (t < KSEL)
        out[OFF_SAMP + g * KSEL + t] = (float)(g * NN + sidx[t]);

    float mask = (float)flags[t];
    float ind  = (mask - p) + p;
    float pf   = p * ind;
    pf_buf[g * NN + t] = pf;
    out[OFF_PF + g * NN + t] = pf;
}

// ---------------- edge weights ---------------------------------------------
__global__ void ew_kernel(const int* __restrict__ ei, const float* __restrict__ w,
                          const float* __restrict__ pf, float* __restrict__ out)
{
    int e = blockIdx.x * blockDim.x + threadIdx.x;
    if (e < NE_EDGE) {
        int s = ei[e];
        int d = ei[NE_EDGE + e];
        out[e] = w[e] * pf[s] * pf[d];
    }
}

// ---------------------------------------------------------------------------
extern "C" void kernel_launch(void* const* d_in, const int* in_sizes, int n_in,
                              void* d_out, int out_size)
{
    const float* x      = (const float*)d_in[0];
    const int*   ei     = (const int*)  d_in[1];
    const float* ew     = (const float*)d_in[2];
    const float* emb_w  = (const float*)d_in[3];
    const float* emb_b  = (const float*)d_in[4];
    const float* qkv_w  = (const float*)d_in[5];
    const float* qkv_b  = (const float*)d_in[6];
    const float* out_w  = (const float*)d_in[7];
    const float* out_b  = (const float*)d_in[8];
    const float* ln1_w  = (const float*)d_in[9];
    const float* ln1_b  = (const float*)d_in[10];
    const float* ln2_w  = (const float*)d_in[11];
    const float* ln2_b  = (const float*)d_in[12];
    const float* ff1_w  = (const float*)d_in[13];
    const float* ff1_b  = (const float*)d_in[14];
    const float* ff2_w  = (const float*)d_in[15];
    const float* ff2_b  = (const float*)d_in[16];
    const float* sc_w   = (const float*)d_in[17];
    const float* sc_b   = (const float*)d_in[18];
    float* out = (float*)d_out;

    float *h, *qkvb, *attn, *ff, *probs, *pf;
    cudaGetSymbolAddress((void**)&h,     g_h);
    cudaGetSymbolAddress((void**)&qkvb,  g_qkv);
    cudaGetSymbolAddress((void**)&attn,  g_attn);
    cudaGetSymbolAddress((void**)&ff,    g_ff);
    cudaGetSymbolAddress((void**)&probs, g_probs);
    cudaGetSymbolAddress((void**)&pf,    g_pf);

    cudaFuncSetAttribute(gemm_mma, cudaFuncAttributeMaxDynamicSharedMemorySize, GEMM_SMEM);

    // embedding: [GN,128] @ [256,128]^T -> h [GN,256]
    gemm_mma<<<dim3(E / BN, GN / BM), 256, GEMM_SMEM>>>(x, emb_w, emb_b, h, D_IN, E, 0);

    for (int l = 0; l < NL; l++) {
        const float* qw = qkv_w + (size_t)l * 3 * E * E;
        const float* qb = qkv_b + (size_t)l * 3 * E;
        const float* ow = out_w + (size_t)l * E * E;
        const float* ob = out_b + (size_t)l * E;
        const float* f1w = ff1_w + (size_t)l * DFF * E;
        const float* f1b = ff1_b + (size_t)l * DFF;
        const float* f2w = ff2_w + (size_t)l * E * DFF;
        const float* f2b = ff2_b + (size_t)l * E;

        // qkv projection -> g_qkv [GN, 768]
        gemm_mma<<<dim3(3 * E / BN, GN / BM), 256, GEMM_SMEM>>>(h, qw, qb, qkvb, E, 3 * E, 0);
        // attention -> g_attn [GN, 256]
        attn_kernel<<<dim3(NG * NH, NN / 128), 128>>>(qkvb, attn);
        // output projection -> g_ff (first GN*E floats)
        gemm_mma<<<dim3(E / BN, GN / BM), 256, GEMM_SMEM>>>(attn, ow, ob, ff, E, E, 0);
        // h = LN1(h + proj)
        ln_kernel<<<GN, E>>>(h, ff, ln1_w + (size_t)l * E, ln1_b + (size_t)l * E);
        // ff1 + relu -> g_ff [GN, 2048]
        gemm_mma<<<dim3(DFF / BN, GN / BM), 256, GEMM_SMEM>>>(h, f1w, f1b, ff, E, DFF, 1);
        // ff2 -> g_attn [GN, 256]
        gemm_mma<<<dim3(E / BN, GN / BM), 256, GEMM_SMEM>>>(ff, f2w, f2b, attn, DFF, E, 0);
        // h = LN2(h + ff)
        ln_kernel<<<GN, E>>>(h, attn, ln2_w + (size_t)l * E, ln2_b + (size_t)l * E);
    }

    // score + sigmoid
    score_kernel<<<(GN * 32 + 255) / 256, 256>>>(h, sc_w, sc_b, probs);
    // per-graph top-k, probs_f, sampled_nodes
    topk_kernel<<<NG, NN>>>(probs, out, pf);
    // edge weights
    ew_kernel<<<(NE_EDGE + 255) / 256, 256>>>(ei, ew, pf, out);
}

// round 14
// speedup vs baseline: 1.0001x; 1.0001x over previous
#include <cuda_runtime.h>
#include <cuda_bf16.h>
#include <cstdint>
#include <math.h>

// Problem constants
#define NG      64          // num graphs
#define NN      512         // nodes per graph
#define GN      32768       // NG*NN
#define D_IN    128
#define E       256
#define NL      4
#define DFF     2048
#define NE_EDGE 524288
#define KSEL    128
#define NH      8
#define HD      32

#define OFF_SAMP (NE_EDGE)
#define OFF_PF   (NE_EDGE + NG * KSEL)

// ---------------- scratch (static device globals; no cudaMalloc allowed) ---
__device__ float g_h[(size_t)GN * E];       // 32 MB  hidden state
__device__ float g_qkv[(size_t)GN * 3 * E]; // 96 MB
__device__ float g_attn[(size_t)GN * E];    // 32 MB  attn output / ff2 output
__device__ float g_ff[(size_t)GN * DFF];    // 256 MB out-proj result then ff1 act
__device__ float g_probs[GN];
__device__ float g_pf[GN];

// ---------------- tf32 helpers ---------------------------------------------
__device__ __forceinline__ float tf32_rna(float x) {
    uint32_t r;
    asm("cvt.rna.tf32.f32 %0, %1;" : "=r"(r) : "f"(x));
    return __uint_as_float(r);
}

// mma.sync m16n8k8 tf32 (baseline sm_80+ PTX — works on plain sm_103 target)
__device__ __forceinline__ void mma_tf32(float* d, const uint32_t* a, const uint32_t* b) {
    asm volatile(
        "mma.sync.aligned.m16n8k8.row.col.f32.tf32.tf32.f32 "
        "{%0,%1,%2,%3}, {%4,%5,%6,%7}, {%8,%9}, {%0,%1,%2,%3};"
        : "+f"(d[0]), "+f"(d[1]), "+f"(d[2]), "+f"(d[3])
        : "r"(a[0]), "r"(a[1]), "r"(a[2]), "r"(a[3]), "r"(b[0]), "r"(b[1]));
}

__device__ __forceinline__ void cp_async16(uint32_t smem_addr, const void* gptr) {
    asm volatile("cp.async.cg.shared.global [%0], [%1], 16;"
                 :: "r"(smem_addr), "l"(gptr));
}
__device__ __forceinline__ void cp_commit() {
    asm volatile("cp.async.commit_group;");
}

// ---------------- tf32x3 tensor-core GEMM, cp.async 2-stage ----------------
// C[M,N] = A[M,K] @ B[N,K]^T + bias, optional relu.
// Block tile 128x64, BK=32, 256 threads = 8 warps (4x2), warp tile 32x32.
// tf32 hi/lo split in registers at fragment-load time. SPLIT-MAJOR mma
// ordering: all 8 tiles' hh, then all hl, then all lh — consecutive mma hit
// different accumulators (chain distance 8), keeping the tensor pipe
// streaming instead of serializing on the acc RAW chain. Per-accumulator
// order (hh, hl, lh per kk) unchanged => bitwise-identical numerics.
#define BM   128
#define BN   64
#define BK   32
#define PAD_ROW 36                         // floats per smem row (32 + 4 pad)
#define ST_A  0
#define ST_B  (BM * PAD_ROW)               // 4608
#define STAGE_F (BM * PAD_ROW + BN * PAD_ROW)   // 6912 floats
#define GEMM_SMEM (2 * STAGE_F * 4)        // 55296 B

__global__ void __launch_bounds__(256, 3)
gemm_mma(const float* __restrict__ A, const float* __restrict__ B,
         const float* __restrict__ bias, float* __restrict__ C,
         int K, int N, int relu)
{
    extern __shared__ float sm[];
    const uint32_t smb = (uint32_t)__cvta_generic_to_shared(sm);

    const int tid  = threadIdx.x;
    const int warp = tid >> 5;
    const int lane = tid & 31;
    const int wm   = warp >> 1;            // 0..3  (m direction, 32 rows each)
    const int wn   = warp & 1;             // 0..1  (n direction, 32 cols each)
    const int gid  = lane >> 2;            // 0..7
    const int qid  = lane & 3;             // 0..3
    const int m0   = blockIdx.y * BM;
    const int n0   = blockIdx.x * BN;

    // cp.async indices: A 4 float4/thread, B 2 float4/thread per chunk
    const int lr = tid >> 3;               // 0..31
    const int lc = (tid & 7) * 4;          // 0,4,...,28
    const int NC = K >> 5;

    float acc[2][4][4];
#pragma unroll
    for (int i = 0; i < 2; i++)
#pragma unroll
        for (int j = 0; j < 4; j++)
#pragma unroll
            for (int t = 0; t < 4; t++) acc[i][j][t] = 0.f;

    // stage loader: chunk c -> stage s
    auto load_stage = [&](int c, int s) {
        const float* Ab = A + (size_t)m0 * K + c * BK;
        const float* Bb = B + (size_t)n0 * K + c * BK;
        uint32_t st = smb + (uint32_t)(s * STAGE_F * 4);
#pragma unroll
        for (int i = 0; i < 4; i++) {
            int r = lr + 32 * i;           // 0..127
            cp_async16(st + (uint32_t)((ST_A + r * PAD_ROW + lc) * 4),
                       Ab + (size_t)r * K + lc);
        }
#pragma unroll
        for (int i = 0; i < 2; i++) {
            int r = lr + 32 * i;           // 0..63
            cp_async16(st + (uint32_t)((ST_B + r * PAD_ROW + lc) * 4),
                       Bb + (size_t)r * K + lc);
        }
        cp_commit();
    };

    // prologue: stages 0 and 1 in flight
    load_stage(0, 0);
    if (NC > 1) load_stage(1, 1);

    for (int c = 0; c < NC; c++) {
        // wait until chunk c's group has landed (allow c+1 outstanding)
        if (c + 1 < NC) asm volatile("cp.async.wait_group 1;" ::: "memory");
        else            asm volatile("cp.async.wait_group 0;" ::: "memory");
        __syncthreads();

        const float* st  = sm + (c & 1) * STAGE_F;
        const float* As  = st + ST_A;
        const float* Bs  = st + ST_B;

#pragma unroll
        for (int kk = 0; kk < 4; kk++) {
            const int kb = kk * 8;
            uint32_t a_hi[2][4], a_lo[2][4];
#pragma unroll
            for (int tm = 0; tm < 2; tm++) {
                int r = wm * 32 + tm * 16 + gid;
                float v0 = As[r * PAD_ROW + kb + qid];
                float v1 = As[(r + 8) * PAD_ROW + kb + qid];
                float v2 = As[r * PAD_ROW + kb + qid + 4];
                float v3 = As[(r + 8) * PAD_ROW + kb + qid + 4];
                float h0 = tf32_rna(v0), h1 = tf32_rna(v1);
                float h2 = tf32_rna(v2), h3 = tf32_rna(v3);
                a_hi[tm][0] = __float_as_uint(h0); a_lo[tm][0] = __float_as_uint(v0 - h0);
                a_hi[tm][1] = __float_as_uint(h1); a_lo[tm][1] = __float_as_uint(v1 - h1);
                a_hi[tm][2] = __float_as_uint(h2); a_lo[tm][2] = __float_as_uint(v2 - h2);
                a_hi[tm][3] = __float_as_uint(h3); a_lo[tm][3] = __float_as_uint(v3 - h3);
            }
            uint32_t b_hi[4][2], b_lo[4][2];
#pragma unroll
            for (int tn = 0; tn < 4; tn++) {
                int cc = wn * 32 + tn * 8 + gid;
                float v0 = Bs[cc * PAD_ROW + kb + qid];
                float v1 = Bs[cc * PAD_ROW + kb + qid + 4];
                float h0 = tf32_rna(v0), h1 = tf32_rna(v1);
                b_hi[tn][0] = __float_as_uint(h0); b_lo[tn][0] = __float_as_uint(v0 - h0);
                b_hi[tn][1] = __float_as_uint(h1); b_lo[tn][1] = __float_as_uint(v1 - h1);
            }
            // split-major: consecutive mma hit different accumulators
#pragma unroll
            for (int tm = 0; tm < 2; tm++)
#pragma unroll
                for (int tn = 0; tn < 4; tn++)
                    mma_tf32(acc[tm][tn], a_hi[tm], b_hi[tn]);
#pragma unroll
            for (int tm = 0; tm < 2; tm++)
#pragma unroll
                for (int tn = 0; tn < 4; tn++)
                    mma_tf32(acc[tm][tn], a_hi[tm], b_lo[tn]);
#pragma unroll
            for (int tm = 0; tm < 2; tm++)
#pragma unroll
                for (int tn = 0; tn < 4; tn++)
                    mma_tf32(acc[tm][tn], a_lo[tm], b_hi[tn]);
        }

        // refill the stage we just consumed with chunk c+2
        if (c + 2 < NC) {
            __syncthreads();               // all warps done reading stage c&1
            load_stage(c + 2, c & 1);
        }
    }

    // ---- epilogue: bias (+relu), write fp32 ----
#pragma unroll
    for (int tm = 0; tm < 2; tm++) {
#pragma unroll
        for (int tn = 0; tn < 4; tn++) {
            const float* d = acc[tm][tn];
            int row = m0 + wm * 32 + tm * 16 + gid;
            int col = n0 + wn * 32 + tn * 8 + 2 * qid;
            float bx = bias[col], by = bias[col + 1];
            float2 v0 = make_float2(d[0] + bx, d[1] + by);
            float2 v1 = make_float2(d[2] + bx, d[3] + by);
            if (relu) {
                v0.x = fmaxf(v0.x, 0.f); v0.y = fmaxf(v0.y, 0.f);
                v1.x = fmaxf(v1.x, 0.f); v1.y = fmaxf(v1.y, 0.f);
            }
            *(float2*)(C + (size_t)row * N + col) = v0;
            *(float2*)(C + (size_t)(row + 8) * N + col) = v1;
        }
    }
}

// ---------------- flash-style attention (fp32, proven version) -------------
__global__ void attn_kernel(const float* __restrict__ qkv, float* __restrict__ out)
{
    __shared__ float Ks[64][32];
    __shared__ float Vs[64][32];

    const int g  = blockIdx.x >> 3;
    const int h  = blockIdx.x & 7;
    const int tid = threadIdx.x;
    const int qi = blockIdx.y * 128 + tid;       // 0..511
    const int hc = h * HD;
    const float* base = qkv + (size_t)g * NN * (3 * E);

    float q[HD];
#pragma unroll
    for (int d = 0; d < HD; d++) q[d] = base[(size_t)qi * (3 * E) + hc + d];

    float acc[HD];
#pragma unroll
    for (int d = 0; d < HD; d++) acc[d] = 0.f;
    float mval = -1e30f, l = 0.f;
    const float scale = 0.17677669529663687f;    // 1/sqrt(32)

#pragma unroll 1
    for (int kt = 0; kt < NN; kt += 64) {
        const int row  = tid >> 1;
        const int half = (tid & 1) * 16;
        const float* kp = base + (size_t)(kt + row) * (3 * E) + E + hc + half;
        const float* vp = base + (size_t)(kt + row) * (3 * E) + 2 * E + hc + half;
#pragma unroll
        for (int c = 0; c < 16; c += 4) {
            *(float4*)&Ks[row][half + c] = *(const float4*)(kp + c);
            *(float4*)&Vs[row][half + c] = *(const float4*)(vp + c);
        }
        __syncthreads();

#pragma unroll 1
        for (int jc = 0; jc < 64; jc += 16) {
            float s[16];
            float cmax = -1e30f;
#pragma unroll
            for (int j = 0; j < 16; j++) {
                float sv = 0.f;
#pragma unroll
                for (int d = 0; d < HD; d++) sv = fmaf(q[d], Ks[jc + j][d], sv);
                sv *= scale;
                s[j] = sv;
                cmax = fmaxf(cmax, sv);
            }
            float mnew = fmaxf(mval, cmax);
            float corr = __expf(mval - mnew);
            l *= corr;
#pragma unroll
            for (int d = 0; d < HD; d++) acc[d] *= corr;
#pragma unroll
            for (int j = 0; j < 16; j++) {
                float p = __expf(s[j] - mnew);
                l += p;
#pragma unroll
                for (int d = 0; d < HD; d++)
                    acc[d] = fmaf(p, Vs[jc + j][d], acc[d]);
            }
            mval = mnew;
        }
        __syncthreads();
    }

    float inv = 1.f / l;
    float* op = out + (size_t)(g * NN + qi) * E + hc;
#pragma unroll
    for (int d = 0; d < HD; d++) op[d] = acc[d] * inv;
}

// ---------------- fused residual + LayerNorm (two-pass, fp32) --------------
__global__ void ln_kernel(float* __restrict__ h, const float* __restrict__ add,
                          const float* __restrict__ w, const float* __restrict__ b)
{
    __shared__ float red[256];
    const int r = blockIdx.x;
    const int t = threadIdx.x;
    const size_t off = (size_t)r * E + t;
    float x = h[off] + add[off];

    red[t] = x;
    __syncthreads();
#pragma unroll
    for (int s = 128; s > 0; s >>= 1) {
        if (t < s) red[t] += red[t + s];
        __syncthreads();
    }
    float mu = red[0] * (1.f / E);
    __syncthreads();

    float d = x - mu;
    red[t] = d * d;
    __syncthreads();
#pragma unroll
    for (int s = 128; s > 0; s >>= 1) {
        if (t < s) red[t] += red[t + s];
        __syncthreads();
    }
    float var = red[0] * (1.f / E);
    float y = d * rsqrtf(var + 1e-5f) * w[t] + b[t];
    h[off] = y;
}

// ---------------- score + sigmoid (warp per row) ---------------------------
__global__ void score_kernel(const float* __restrict__ h, const float* __restrict__ sw,
                             const float* __restrict__ sb, float* __restrict__ probs)
{
    const int warp = (blockIdx.x * blockDim.x + threadIdx.x) >> 5;
    const int lane = threadIdx.x & 31;
    if (warp >= GN) return;
    const float* hp = h + (size_t)warp * E;
    float s = 0.f;
#pragma unroll
    for (int k = 0; k < 8; k++) s = fmaf(hp[lane + k * 32], sw[lane + k * 32], s);
#pragma unroll
    for (int o = 16; o; o >>= 1) s += __shfl_xor_sync(0xffffffff, s, o);
    if (lane == 0) {
        s += sb[0];
        probs[warp] = 1.f / (1.f + expf(-s));
    }
}

// ---------------- per-graph top-k (k=128 of n=512) -------------------------
__global__ void topk_kernel(const float* __restrict__ probs,
                            float* __restrict__ out, float* __restrict__ pf_buf)
{
    __shared__ unsigned long long keys[NN];
    __shared__ int sidx[KSEL];
    __shared__ int flags[NN];

    const int g = blockIdx.x;
    const int t = threadIdx.x;
    const float p = probs[g * NN + t];

    unsigned int fb = __float_as_uint(p);
    keys[t] = ((unsigned long long)fb << 32) | (unsigned)(NN - 1 - t);
    __syncthreads();

    for (int k = 2; k <= NN; k <<= 1) {
        for (int j = k >> 1; j > 0; j >>= 1) {
            int ixj = t ^ j;
            if (ixj > t) {
                unsigned long long a = keys[t], b = keys[ixj];
                bool up = ((t & k) == 0);
                if (up ? (a < b) : (a > b)) { keys[t] = b; keys[ixj] = a; }
            }
            __syncthreads();
        }
    }

    if (t < KSEL) sidx[t] = NN - 1 - (int)(unsigned)(keys[t] & 0xFFFFFFFFu);
    __syncthreads();

    for (int k = 2; k <= KSEL; k <<= 1) {
        for (int j = k >> 1; j > 0; j >>= 1) {
            int ixj = t ^ j;
            if (t < KSEL && ixj > t && ixj < KSEL) {
                int a = sidx[t], b = sidx[ixj];
                bool up = ((t & k) == 0);
                if (up ? (a > b) : (a < b)) { sidx[t] = b; sidx[ixj] = a; }
            }
            __syncthreads();
        }
    }

    flags[t] = 0;
    __syncthreads();
    if (t < KSEL) flags[sidx[t]] = 1;
    __syncthreads();

    if (t < KSEL)
        out[OFF_SAMP + g * KSEL + t] = (float)(g * NN + sidx[t]);

    float mask = (float)flags[t];
    float ind  = (mask - p) + p;
    float pf   = p * ind;
    pf_buf[g * NN + t] = pf;
    out[OFF_PF + g * NN + t] = pf;
}

// ---------------- edge weights ---------------------------------------------
__global__ void ew_kernel(const int* __restrict__ ei, const float* __restrict__ w,
                          const float* __restrict__ pf, float* __restrict__ out)
{
    int e = blockIdx.x * blockDim.x + threadIdx.x;
    if (e < NE_EDGE) {
        int s = ei[e];
        int d = ei[NE_EDGE + e];
        out[e] = w[e] * pf[s] * pf[d];
    }
}

// ---------------------------------------------------------------------------
extern "C" void kernel_launch(void* const* d_in, const int* in_sizes, int n_in,
                              void* d_out, int out_size)
{
    const float* x      = (const float*)d_in[0];
    const int*   ei     = (const int*)  d_in[1];
    const float* ew     = (const float*)d_in[2];
    const float* emb_w  = (const float*)d_in[3];
    const float* emb_b  = (const float*)d_in[4];
    const float* qkv_w  = (const float*)d_in[5];
    const float* qkv_b  = (const float*)d_in[6];
    const float* out_w  = (const float*)d_in[7];
    const float* out_b  = (const float*)d_in[8];
    const float* ln1_w  = (const float*)d_in[9];
    const float* ln1_b  = (const float*)d_in[10];
    const float* ln2_w  = (const float*)d_in[11];
    const float* ln2_b  = (const float*)d_in[12];
    const float* ff1_w  = (const float*)d_in[13];
    const float* ff1_b  = (const float*)d_in[14];
    const float* ff2_w  = (const float*)d_in[15];
    const float* ff2_b  = (const float*)d_in[16];
    const float* sc_w   = (const float*)d_in[17];
    const float* sc_b   = (const float*)d_in[18];
    float* out = (float*)d_out;

    float *h, *qkvb, *attn, *ff, *probs, *pf;
    cudaGetSymbolAddress((void**)&h,     g_h);
    cudaGetSymbolAddress((void**)&qkvb,  g_qkv);
    cudaGetSymbolAddress((void**)&attn,  g_attn);
    cudaGetSymbolAddress((void**)&ff,    g_ff);
    cudaGetSymbolAddress((void**)&probs, g_probs);
    cudaGetSymbolAddress((void**)&pf,    g_pf);

    cudaFuncSetAttribute(gemm_mma, cudaFuncAttributeMaxDynamicSharedMemorySize, GEMM_SMEM);

    // embedding: [GN,128] @ [256,128]^T -> h [GN,256]
    gemm_mma<<<dim3(E / BN, GN / BM), 256, GEMM_SMEM>>>(x, emb_w, emb_b, h, D_IN, E, 0);

    for (int l = 0; l < NL; l++) {
        const float* qw = qkv_w + (size_t)l * 3 * E * E;
        const float* qb = qkv_b + (size_t)l * 3 * E;
        const float* ow = out_w + (size_t)l * E * E;
        const float* ob = out_b + (size_t)l * E;
        const float* f1w = ff1_w + (size_t)l * DFF * E;
        const float* f1b = ff1_b + (size_t)l * DFF;
        const float* f2w = ff2_w + (size_t)l * E * DFF;
        const float* f2b = ff2_b + (size_t)l * E;

        // qkv projection -> g_qkv [GN, 768]
        gemm_mma<<<dim3(3 * E / BN, GN / BM), 256, GEMM_SMEM>>>(h, qw, qb, qkvb, E, 3 * E, 0);
        // attention -> g_attn [GN, 256]
        attn_kernel<<<dim3(NG * NH, NN / 128), 128>>>(qkvb, attn);
        // output projection -> g_ff (first GN*E floats)
        gemm_mma<<<dim3(E / BN, GN / BM), 256, GEMM_SMEM>>>(attn, ow, ob, ff, E, E, 0);
        // h = LN1(h + proj)
        ln_kernel<<<GN, E>>>(h, ff, ln1_w + (size_t)l * E, ln1_b + (size_t)l * E);
        // ff1 + relu -> g_ff [GN, 2048]
        gemm_mma<<<dim3(DFF / BN, GN / BM), 256, GEMM_SMEM>>>(h, f1w, f1b, ff, E, DFF, 1);
        // ff2 -> g_attn [GN, 256]
        gemm_mma<<<dim3(E / BN, GN / BM), 256, GEMM_SMEM>>>(ff, f2w, f2b, attn, DFF, E, 0);
        // h = LN2(h + ff)
        ln_kernel<<<GN, E>>>(h, attn, ln2_w + (size_t)l * E, ln2_b + (size_t)l * E);
    }

    // score + sigmoid
    score_kernel<<<(GN * 32 + 255) / 256, 256>>>(h, sc_w, sc_b, probs);
    // per-graph top-k, probs_f, sampled_nodes
    topk_kernel<<<NG, NN>>>(probs, out, pf);
    // edge weights
    ew_kernel<<<(NE_EDGE + 255) / 256, 256>>>(ei, ew, pf, out);
}

// round 16
// speedup vs baseline: 1.2288x; 1.2287x over previous
#include <cuda_runtime.h>
#include <cuda_fp16.h>
#include <cstdint>
#include <math.h>

// Problem constants
#define NG      64
#define NN      512
#define GN      32768
#define D_IN    128
#define E       256
#define NL      4
#define DFF     2048
#define NE_EDGE 524288
#define KSEL    128
#define NH      8
#define HD      32

#define OFF_SAMP (NE_EDGE)
#define OFF_PF   (NE_EDGE + NG * KSEL)

// ---------------- scratch (static device globals) --------------------------
__device__ float g_h[(size_t)GN * E];
__device__ float g_qkv[(size_t)GN * 3 * E];
__device__ float g_attn[(size_t)GN * E];
__device__ float g_ff[(size_t)GN * E];          // out-proj result (residual)
__device__ float g_probs[GN];
__device__ float g_pf[GN];

// fp16 hi/lo split buffers (A-side activations)
__device__ __half g_x16h[(size_t)GN * D_IN];
__device__ __half g_x16l[(size_t)GN * D_IN];
__device__ __half g_h16h[(size_t)GN * E];
__device__ __half g_h16l[(size_t)GN * E];
__device__ __half g_a16h[(size_t)GN * E];
__device__ __half g_a16l[(size_t)GN * E];
__device__ __half g_f16h[(size_t)GN * DFF];
__device__ __half g_f16l[(size_t)GN * DFF];

// fp16 hi/lo weight arena
#define W_EMB  0
#define W_QKV  (W_EMB + E * D_IN)                       // 32768
#define W_OUT  (W_QKV + NL * 3 * E * E)                 // 819200
#define W_FF1  (W_OUT + NL * E * E)                     // 1081344
#define W_FF2  (W_FF1 + NL * DFF * E)                   // 3178496
#define W_TOT  (W_FF2 + NL * E * DFF)                   // 5275648
__device__ __half g_w16h[W_TOT];
__device__ __half g_w16l[W_TOT];

// ---------------- helpers ---------------------------------------------------
__device__ __forceinline__ void mma16(float* d, const uint32_t* a, const uint32_t* b) {
    asm volatile(
        "mma.sync.aligned.m16n8k16.row.col.f32.f16.f16.f32 "
        "{%0,%1,%2,%3}, {%4,%5,%6,%7}, {%8,%9}, {%0,%1,%2,%3};"
        : "+f"(d[0]), "+f"(d[1]), "+f"(d[2]), "+f"(d[3])
        : "r"(a[0]), "r"(a[1]), "r"(a[2]), "r"(a[3]), "r"(b[0]), "r"(b[1]));
}
__device__ __forceinline__ void ldm_x4(uint32_t* r, uint32_t addr) {
    asm volatile("ldmatrix.sync.aligned.m8n8.x4.shared.b16 {%0,%1,%2,%3}, [%4];"
                 : "=r"(r[0]), "=r"(r[1]), "=r"(r[2]), "=r"(r[3]) : "r"(addr));
}
__device__ __forceinline__ void ldm_x2(uint32_t* r, uint32_t addr) {
    asm volatile("ldmatrix.sync.aligned.m8n8.x2.shared.b16 {%0,%1}, [%2];"
                 : "=r"(r[0]), "=r"(r[1]) : "r"(addr));
}
__device__ __forceinline__ void cp_async16(uint32_t smem_addr, const void* gptr) {
    asm volatile("cp.async.cg.shared.global [%0], [%1], 16;"
                 :: "r"(smem_addr), "l"(gptr));
}
__device__ __forceinline__ void cp_commit() {
    asm volatile("cp.async.commit_group;");
}

// ---------------- fp16x2 3-term tensor-core GEMM ---------------------------
// C[M,N] = (Ah+Al)[M,K] @ (Bh+Bl)[N,K]^T + bias (terms hh, hl, lh).
// Block tile 128x64, BK=32 (2 k16 steps), 2 cp.async stages, 8 warps (4x2),
// warp tile 32x32. Fragments via ldmatrix from padded fp16 smem.
#define BM   128
#define BN   64
#define BK   32
#define PADH 40                                  // halfs per smem row
#define SA_HI 0
#define SA_LO (BM * PADH)                        // 5120
#define SB_HI (2 * BM * PADH)                    // 10240
#define SB_LO (2 * BM * PADH + BN * PADH)        // 12800
#define STAGE_H (2 * BM * PADH + 2 * BN * PADH)  // 15360 halfs
#define GEMM_SMEM (2 * STAGE_H * 2)              // 61440 B

__global__ void __launch_bounds__(256, 3)
gemm16(const __half* __restrict__ Ah, const __half* __restrict__ Al,
       const __half* __restrict__ Bh, const __half* __restrict__ Bl,
       const float* __restrict__ bias, float* __restrict__ C,
       __half* __restrict__ Ch, __half* __restrict__ Cl,
       int K, int N, int relu)
{
    extern __shared__ __half sh[];
    const uint32_t smb = (uint32_t)__cvta_generic_to_shared(sh);

    const int tid  = threadIdx.x;
    const int warp = tid >> 5;
    const int lane = tid & 31;
    const int wm   = warp >> 1;
    const int wn   = warp & 1;
    const int gid  = lane >> 2;
    const int qid  = lane & 3;
    const int m0   = blockIdx.y * BM;
    const int n0   = blockIdx.x * BN;
    const int NC   = K >> 5;

    // ldmatrix per-lane row offsets (in halfs, within a stage)
    const int lm = lane >> 3;                 // matrix index 0..3
    const int l7 = lane & 7;
    int arow[2];
#pragma unroll
    for (int tm = 0; tm < 2; tm++)
        arow[tm] = (wm * 32 + tm * 16 + (lm & 1) * 8 + l7) * PADH + (lm >> 1) * 8;
    int brow[4];
#pragma unroll
    for (int tn = 0; tn < 4; tn++)
        brow[tn] = (wn * 32 + tn * 8 + l7) * PADH + (lm & 1) * 8;

    float acc[2][4][4];
#pragma unroll
    for (int i = 0; i < 2; i++)
#pragma unroll
        for (int j = 0; j < 4; j++)
#pragma unroll
            for (int t = 0; t < 4; t++) acc[i][j][t] = 0.f;

    // cp.async indices
    const int ar = tid >> 1;                  // 0..127
    const int aq = (tid & 1) * 2;             // quarter 0/2 (+1)
    const int br2 = tid >> 2;                 // 0..63
    const int bq = tid & 3;                   // quarter 0..3

    auto load_stage = [&](int c, int s) {
        const int k0 = c * BK;
        uint32_t st = smb + (uint32_t)(s * STAGE_H) * 2;
#pragma unroll
        for (int i = 0; i < 2; i++) {
            int q = aq + i;
            cp_async16(st + (uint32_t)(SA_HI + ar * PADH + q * 8) * 2,
                       Ah + (size_t)(m0 + ar) * K + k0 + q * 8);
            cp_async16(st + (uint32_t)(SA_LO + ar * PADH + q * 8) * 2,
                       Al + (size_t)(m0 + ar) * K + k0 + q * 8);
        }
        cp_async16(st + (uint32_t)(SB_HI + br2 * PADH + bq * 8) * 2,
                   Bh + (size_t)(n0 + br2) * K + k0 + bq * 8);
        cp_async16(st + (uint32_t)(SB_LO + br2 * PADH + bq * 8) * 2,
                   Bl + (size_t)(n0 + br2) * K + k0 + bq * 8);
        cp_commit();
    };

    load_stage(0, 0);
    if (NC > 1) load_stage(1, 1);

    for (int c = 0; c < NC; c++) {
        if (c + 1 < NC) asm volatile("cp.async.wait_group 1;" ::: "memory");
        else            asm volatile("cp.async.wait_group 0;" ::: "memory");
        __syncthreads();

        const uint32_t sbase = smb + (uint32_t)((c & 1) * STAGE_H) * 2;

#pragma unroll
        for (int kk = 0; kk < 2; kk++) {
            const int kb = kk * 16;
            uint32_t ah[2][4], al[2][4];
#pragma unroll
            for (int tm = 0; tm < 2; tm++) {
                ldm_x4(ah[tm], sbase + (uint32_t)(SA_HI + arow[tm] + kb) * 2);
                ldm_x4(al[tm], sbase + (uint32_t)(SA_LO + arow[tm] + kb) * 2);
            }
#pragma unroll
            for (int tn = 0; tn < 4; tn++) {
                uint32_t bh[2], bl[2];
                ldm_x2(bh, sbase + (uint32_t)(SB_HI + brow[tn] + kb) * 2);
                ldm_x2(bl, sbase + (uint32_t)(SB_LO + brow[tn] + kb) * 2);
#pragma unroll
                for (int tm = 0; tm < 2; tm++) {
                    mma16(acc[tm][tn], ah[tm], bh);   // hh
                    mma16(acc[tm][tn], ah[tm], bl);   // hl
                    mma16(acc[tm][tn], al[tm], bh);   // lh
                }
            }
        }

        if (c + 2 < NC) {
            __syncthreads();
            load_stage(c + 2, c & 1);
        }
    }

    // ---- epilogue ----
#pragma unroll
    for (int tm = 0; tm < 2; tm++) {
#pragma unroll
        for (int tn = 0; tn < 4; tn++) {
            const float* d = acc[tm][tn];
            int row = m0 + wm * 32 + tm * 16 + gid;
            int col = n0 + wn * 32 + tn * 8 + 2 * qid;
            float bx = bias[col], by = bias[col + 1];
            float2 v0 = make_float2(d[0] + bx, d[1] + by);
            float2 v1 = make_float2(d[2] + bx, d[3] + by);
            if (relu) {
                v0.x = fmaxf(v0.x, 0.f); v0.y = fmaxf(v0.y, 0.f);
                v1.x = fmaxf(v1.x, 0.f); v1.y = fmaxf(v1.y, 0.f);
            }
            if (C) {
                *(float2*)(C + (size_t)row * N + col) = v0;
                *(float2*)(C + (size_t)(row + 8) * N + col) = v1;
            }
            if (Ch) {
                __half h0 = __float2half_rn(v0.x), h1 = __float2half_rn(v0.y);
                __half h2 = __float2half_rn(v1.x), h3 = __float2half_rn(v1.y);
                *(__half2*)(Ch + (size_t)row * N + col) = __halves2half2(h0, h1);
                *(__half2*)(Ch + (size_t)(row + 8) * N + col) = __halves2half2(h2, h3);
                __half l0 = __float2half_rn(v0.x - __half2float(h0));
                __half l1 = __float2half_rn(v0.y - __half2float(h1));
                __half l2 = __float2half_rn(v1.x - __half2float(h2));
                __half l3 = __float2half_rn(v1.y - __half2float(h3));
                *(__half2*)(Cl + (size_t)row * N + col) = __halves2half2(l0, l1);
                *(__half2*)(Cl + (size_t)(row + 8) * N + col) = __halves2half2(l2, l3);
            }
        }
    }
}

// ---------------- fp32 -> fp16 hi/lo converter -----------------------------
__global__ void conv_split(const float* __restrict__ src, __half* __restrict__ hi,
                           __half* __restrict__ lo, int n)
{
    int i = blockIdx.x * blockDim.x + threadIdx.x;
    if (i < n) {
        float v = src[i];
        __half h = __float2half_rn(v);
        hi[i] = h;
        lo[i] = __float2half_rn(v - __half2float(h));
    }
}

// ---------------- flash-style attention (fp32 + fp16 split epilogue) -------
__global__ void attn_kernel(const float* __restrict__ qkv, float* __restrict__ out,
                            __half* __restrict__ o16h, __half* __restrict__ o16l)
{
    __shared__ float Ks[64][32];
    __shared__ float Vs[64][32];

    const int g  = blockIdx.x >> 3;
    const int h  = blockIdx.x & 7;
    const int tid = threadIdx.x;
    const int qi = blockIdx.y * 128 + tid;
    const int hc = h * HD;
    const float* base = qkv + (size_t)g * NN * (3 * E);

    float q[HD];
#pragma unroll
    for (int d = 0; d < HD; d++) q[d] = base[(size_t)qi * (3 * E) + hc + d];

    float acc[HD];
#pragma unroll
    for (int d = 0; d < HD; d++) acc[d] = 0.f;
    float mval = -1e30f, l = 0.f;
    const float scale = 0.17677669529663687f;

#pragma unroll 1
    for (int kt = 0; kt < NN; kt += 64) {
        const int row  = tid >> 1;
        const int half = (tid & 1) * 16;
        const float* kp = base + (size_t)(kt + row) * (3 * E) + E + hc + half;
        const float* vp = base + (size_t)(kt + row) * (3 * E) + 2 * E + hc + half;
#pragma unroll
        for (int c = 0; c < 16; c += 4) {
            *(float4*)&Ks[row][half + c] = *(const float4*)(kp + c);
            *(float4*)&Vs[row][half + c] = *(const float4*)(vp + c);
        }
        __syncthreads();

#pragma unroll 1
        for (int jc = 0; jc < 64; jc += 16) {
            float s[16];
            float cmax = -1e30f;
#pragma unroll
            for (int j = 0; j < 16; j++) {
                float sv = 0.f;
#pragma unroll
                for (int d = 0; d < HD; d++) sv = fmaf(q[d], Ks[jc + j][d], sv);
                sv *= scale;
                s[j] = sv;
                cmax = fmaxf(cmax, sv);
            }
            float mnew = fmaxf(mval, cmax);
            float corr = __expf(mval - mnew);
            l *= corr;
#pragma unroll
            for (int d = 0; d < HD; d++) acc[d] *= corr;
#pragma unroll
            for (int j = 0; j < 16; j++) {
                float p = __expf(s[j] - mnew);
                l += p;
#pragma unroll
                for (int d = 0; d < HD; d++)
                    acc[d] = fmaf(p, Vs[jc + j][d], acc[d]);
            }
            mval = mnew;
        }
        __syncthreads();
    }

    float inv = 1.f / l;
    const size_t ob = (size_t)(g * NN + qi) * E + hc;
#pragma unroll
    for (int d = 0; d < HD; d++) {
        float v = acc[d] * inv;
        out[ob + d] = v;
        __half hh = __float2half_rn(v);
        o16h[ob + d] = hh;
        o16l[ob + d] = __float2half_rn(v - __half2float(hh));
    }
}

// ---------------- fused residual + LayerNorm (+ fp16 split) ----------------
__global__ void ln_kernel(float* __restrict__ h, const float* __restrict__ add,
                          const float* __restrict__ w, const float* __restrict__ b,
                          __half* __restrict__ h16h, __half* __restrict__ h16l)
{
    __shared__ float red[256];
    const int r = blockIdx.x;
    const int t = threadIdx.x;
    const size_t off = (size_t)r * E + t;
    float x = h[off] + add[off];

    red[t] = x;
    __syncthreads();
#pragma unroll
    for (int s = 128; s > 0; s >>= 1) {
        if (t < s) red[t] += red[t + s];
        __syncthreads();
    }
    float mu = red[0] * (1.f / E);
    __syncthreads();

    float d = x - mu;
    red[t] = d * d;
    __syncthreads();
#pragma unroll
    for (int s = 128; s > 0; s >>= 1) {
        if (t < s) red[t] += red[t + s];
        __syncthreads();
    }
    float var = red[0] * (1.f / E);
    float y = d * rsqrtf(var + 1e-5f) * w[t] + b[t];
    h[off] = y;
    __half hh = __float2half_rn(y);
    h16h[off] = hh;
    h16l[off] = __float2half_rn(y - __half2float(hh));
}

// ---------------- score + sigmoid ------------------------------------------
__global__ void score_kernel(const float* __restrict__ h, const float* __restrict__ sw,
                             const float* __restrict__ sb, float* __restrict__ probs)
{
    const int warp = (blockIdx.x * blockDim.x + threadIdx.x) >> 5;
    const int lane = threadIdx.x & 31;
    if (warp >= GN) return;
    const float* hp = h + (size_t)warp * E;
    float s = 0.f;
#pragma unroll
    for (int k = 0; k < 8; k++) s = fmaf(hp[lane + k * 32], sw[lane + k * 32], s);
#pragma unroll
    for (int o = 16; o; o >>= 1) s += __shfl_xor_sync(0xffffffff, s, o);
    if (lane == 0) {
        s += sb[0];
        probs[warp] = 1.f / (1.f + expf(-s));
    }
}

// ---------------- per-graph top-k ------------------------------------------
__global__ void topk_kernel(const float* __restrict__ probs,
                            float* __restrict__ out, float* __restrict__ pf_buf)
{
    __shared__ unsigned long long keys[NN];
    __shared__ int sidx[KSEL];
    __shared__ int flags[NN];

    const int g = blockIdx.x;
    const int t = threadIdx.x;
    const float p = probs[g * NN + t];

    unsigned int fb = __float_as_uint(p);
    keys[t] = ((unsigned long long)fb << 32) | (unsigned)(NN - 1 - t);
    __syncthreads();

    for (int k = 2; k <= NN; k <<= 1) {
        for (int j = k >> 1; j > 0; j >>= 1) {
            int ixj = t ^ j;
            if (ixj > t) {
                unsigned long long a = keys[t], b = keys[ixj];
                bool up = ((t & k) == 0);
                if (up ? (a < b) : (a > b)) { keys[t] = b; keys[ixj] = a; }
            }
            __syncthreads();
        }
    }

    if (t < KSEL) sidx[t] = NN - 1 - (int)(unsigned)(keys[t] & 0xFFFFFFFFu);
    __syncthreads();

    for (int k = 2; k <= KSEL; k <<= 1) {
        for (int j = k >> 1; j > 0; j >>= 1) {
            int ixj = t ^ j;
            if (t < KSEL && ixj > t && ixj < KSEL) {
                int a = sidx[t], b = sidx[ixj];
                bool up = ((t & k) == 0);
                if (up ? (a > b) : (a < b)) { sidx[t] = b; sidx[ixj] = a; }
            }
            __syncthreads();
        }
    }

    flags[t] = 0;
    __syncthreads();
    if (t < KSEL) flags[sidx[t]] = 1;
    __syncthreads();

    if (t < KSEL)
        out[OFF_SAMP + g * KSEL + t] = (float)(g * NN + sidx[t]);

    float mask = (float)flags[t];
    float ind  = (mask - p) + p;
    float pf   = p * ind;
    pf_buf[g * NN + t] = pf;
    out[OFF_PF + g * NN + t] = pf;
}

// ---------------- edge weights ---------------------------------------------
__global__ void ew_kernel(const int* __restrict__ ei, const float* __restrict__ w,
                          const float* __restrict__ pf, float* __restrict__ out)
{
    int e = blockIdx.x * blockDim.x + threadIdx.x;
    if (e < NE_EDGE) {
        int s = ei[e];
        int d = ei[NE_EDGE + e];
        out[e] = w[e] * pf[s] * pf[d];
    }
}

// ---------------------------------------------------------------------------
extern "C" void kernel_launch(void* const* d_in, const int* in_sizes, int n_in,
                              void* d_out, int out_size)
{
    const float* x      = (const float*)d_in[0];
    const int*   ei     = (const int*)  d_in[1];
    const float* ew     = (const float*)d_in[2];
    const float* emb_w  = (const float*)d_in[3];
    const float* emb_b  = (const float*)d_in[4];
    const float* qkv_w  = (const float*)d_in[5];
    const float* qkv_b  = (const float*)d_in[6];
    const float* out_w  = (const float*)d_in[7];
    const float* out_b  = (const float*)d_in[8];
    const float* ln1_w  = (const float*)d_in[9];
    const float* ln1_b  = (const float*)d_in[10];
    const float* ln2_w  = (const float*)d_in[11];
    const float* ln2_b  = (const float*)d_in[12];
    const float* ff1_w  = (const float*)d_in[13];
    const float* ff1_b  = (const float*)d_in[14];
    const float* ff2_w  = (const float*)d_in[15];
    const float* ff2_b  = (const float*)d_in[16];
    const float* sc_w   = (const float*)d_in[17];
    const float* sc_b   = (const float*)d_in[18];
    float* out = (float*)d_out;

    float *h, *qkvb, *attn, *ff, *probs, *pf;
    cudaGetSymbolAddress((void**)&h,     g_h);
    cudaGetSymbolAddress((void**)&qkvb,  g_qkv);
    cudaGetSymbolAddress((void**)&attn,  g_attn);
    cudaGetSymbolAddress((void**)&ff,    g_ff);
    cudaGetSymbolAddress((void**)&probs, g_probs);
    cudaGetSymbolAddress((void**)&pf,    g_pf);

    __half *x16h, *x16l, *h16h, *h16l, *a16h, *a16l, *f16h, *f16l, *wh, *wl;
    cudaGetSymbolAddress((void**)&x16h, g_x16h);
    cudaGetSymbolAddress((void**)&x16l, g_x16l);
    cudaGetSymbolAddress((void**)&h16h, g_h16h);
    cudaGetSymbolAddress((void**)&h16l, g_h16l);
    cudaGetSymbolAddress((void**)&a16h, g_a16h);
    cudaGetSymbolAddress((void**)&a16l, g_a16l);
    cudaGetSymbolAddress((void**)&f16h, g_f16h);
    cudaGetSymbolAddress((void**)&f16l, g_f16l);
    cudaGetSymbolAddress((void**)&wh,   g_w16h);
    cudaGetSymbolAddress((void**)&wl,   g_w16l);

    cudaFuncSetAttribute(gemm16, cudaFuncAttributeMaxDynamicSharedMemorySize, GEMM_SMEM);

    // ---- converters: inputs + all weights to fp16 hi/lo ----
    {
        int n;
        n = GN * D_IN;          conv_split<<<(n + 255) / 256, 256>>>(x, x16h, x16l, n);
        n = E * D_IN;           conv_split<<<(n + 255) / 256, 256>>>(emb_w, wh + W_EMB, wl + W_EMB, n);
        n = NL * 3 * E * E;     conv_split<<<(n + 255) / 256, 256>>>(qkv_w, wh + W_QKV, wl + W_QKV, n);
        n = NL * E * E;         conv_split<<<(n + 255) / 256, 256>>>(out_w, wh + W_OUT, wl + W_OUT, n);
        n = NL * DFF * E;       conv_split<<<(n + 255) / 256, 256>>>(ff1_w, wh + W_FF1, wl + W_FF1, n);
        n = NL * E * DFF;       conv_split<<<(n + 255) / 256, 256>>>(ff2_w, wh + W_FF2, wl + W_FF2, n);
    }

    // embedding: x16 @ embw16 -> h f32 + h16 pair
    gemm16<<<dim3(E / BN, GN / BM), 256, GEMM_SMEM>>>(
        x16h, x16l, wh + W_EMB, wl + W_EMB, emb_b, h, h16h, h16l, D_IN, E, 0);

    for (int l = 0; l < NL; l++) {
        const __half* qwh = wh + W_QKV + (size_t)l * 3 * E * E;
        const __half* qwl = wl + W_QKV + (size_t)l * 3 * E * E;
        const __half* owh = wh + W_OUT + (size_t)l * E * E;
        const __half* owl = wl + W_OUT + (size_t)l * E * E;
        const __half* f1h = wh + W_FF1 + (size_t)l * DFF * E;
        const __half* f1l = wl + W_FF1 + (size_t)l * DFF * E;
        const __half* f2h = wh + W_FF2 + (size_t)l * E * DFF;
        const __half* f2l = wl + W_FF2 + (size_t)l * E * DFF;
        const float* qb  = qkv_b + (size_t)l * 3 * E;
        const float* ob  = out_b + (size_t)l * E;
        const float* f1b = ff1_b + (size_t)l * DFF;
        const float* f2b = ff2_b + (size_t)l * E;

        // qkv: h16 @ qkvw16 -> qkv f32
        gemm16<<<dim3(3 * E / BN, GN / BM), 256, GEMM_SMEM>>>(
            h16h, h16l, qwh, qwl, qb, qkvb, ((__half*)0), ((__half*)0), E, 3 * E, 0);
        // attention -> attn f32 + attn16 pair
        attn_kernel<<<dim3(NG * NH, NN / 128), 128>>>(qkvb, attn, a16h, a16l);
        // out-proj: attn16 @ outw16 -> ff f32 (residual input)
        gemm16<<<dim3(E / BN, GN / BM), 256, GEMM_SMEM>>>(
            a16h, a16l, owh, owl, ob, ff, ((__half*)0), ((__half*)0), E, E, 0);
        // h = LN1(h + proj), + h16 pair
        ln_kernel<<<GN, E>>>(h, ff, ln1_w + (size_t)l * E, ln1_b + (size_t)l * E, h16h, h16l);
        // ff1 + relu: h16 @ ff1w16 -> ff16 pair only
        gemm16<<<dim3(DFF / BN, GN / BM), 256, GEMM_SMEM>>>(
            h16h, h16l, f1h, f1l, f1b, (float*)0, f16h, f16l, E, DFF, 1);
        // ff2: ff16 @ ff2w16 -> attn f32 (residual input)
        gemm16<<<dim3(E / BN, GN / BM), 256, GEMM_SMEM>>>(
            f16h, f16l, f2h, f2l, f2b, attn, ((__half*)0), ((__half*)0), DFF, E, 0);
        // h = LN2(h + ff), + h16 pair
        ln_kernel<<<GN, E>>>(h, attn, ln2_w + (size_t)l * E, ln2_b + (size_t)l * E, h16h, h16l);
    }

    // score + sigmoid
    score_kernel<<<(GN * 32 + 255) / 256, 256>>>(h, sc_w, sc_b, probs);
    // per-graph top-k
    topk_kernel<<<NG, NN>>>(probs, out, pf);
    // edge weights
    ew_kernel<<<(NE_EDGE + 255) / 256, 256>>>(ei, ew, pf, out);
}

// round 17
// speedup vs baseline: 1.3160x; 1.0710x over previous
#include <cuda_runtime.h>
#include <cuda_fp16.h>
#include <cstdint>
#include <math.h>

// Problem constants
#define NG      64
#define NN      512
#define GN      32768
#define D_IN    128
#define E       256
#define NL      4
#define DFF     2048
#define NE_EDGE 524288
#define KSEL    128
#define NH      8
#define HD      32

#define OFF_SAMP (NE_EDGE)
#define OFF_PF   (NE_EDGE + NG * KSEL)

// ---------------- scratch (static device globals) --------------------------
__device__ float g_h[(size_t)GN * E];
__device__ float g_qkv[(size_t)GN * 3 * E];
__device__ float g_attn[(size_t)GN * E];
__device__ float g_ff[(size_t)GN * E];          // out-proj result (residual)
__device__ float g_probs[GN];
__device__ float g_pf[GN];

// fp16 hi/lo split buffers (A-side activations)
__device__ __half g_x16h[(size_t)GN * D_IN];
__device__ __half g_x16l[(size_t)GN * D_IN];
__device__ __half g_h16h[(size_t)GN * E];
__device__ __half g_h16l[(size_t)GN * E];
__device__ __half g_a16h[(size_t)GN * E];
__device__ __half g_a16l[(size_t)GN * E];
__device__ __half g_f16h[(size_t)GN * DFF];
__device__ __half g_f16l[(size_t)GN * DFF];

// fp16 hi/lo weight arena
#define W_EMB  0
#define W_QKV  (W_EMB + E * D_IN)                       // 32768
#define W_OUT  (W_QKV + NL * 3 * E * E)                 // 819200
#define W_FF1  (W_OUT + NL * E * E)                     // 1081344
#define W_FF2  (W_FF1 + NL * DFF * E)                   // 3178496
#define W_TOT  (W_FF2 + NL * E * DFF)                   // 5275648
__device__ __half g_w16h[W_TOT];
__device__ __half g_w16l[W_TOT];

// ---------------- helpers ---------------------------------------------------
__device__ __forceinline__ void mma16(float* d, const uint32_t* a, const uint32_t* b) {
    asm volatile(
        "mma.sync.aligned.m16n8k16.row.col.f32.f16.f16.f32 "
        "{%0,%1,%2,%3}, {%4,%5,%6,%7}, {%8,%9}, {%0,%1,%2,%3};"
        : "+f"(d[0]), "+f"(d[1]), "+f"(d[2]), "+f"(d[3])
        : "r"(a[0]), "r"(a[1]), "r"(a[2]), "r"(a[3]), "r"(b[0]), "r"(b[1]));
}
__device__ __forceinline__ void ldm_x4(uint32_t* r, uint32_t addr) {
    asm volatile("ldmatrix.sync.aligned.m8n8.x4.shared.b16 {%0,%1,%2,%3}, [%4];"
                 : "=r"(r[0]), "=r"(r[1]), "=r"(r[2]), "=r"(r[3]) : "r"(addr));
}
__device__ __forceinline__ void ldm_x2(uint32_t* r, uint32_t addr) {
    asm volatile("ldmatrix.sync.aligned.m8n8.x2.shared.b16 {%0,%1}, [%2];"
                 : "=r"(r[0]), "=r"(r[1]) : "r"(addr));
}
__device__ __forceinline__ void cp_async16(uint32_t smem_addr, const void* gptr) {
    asm volatile("cp.async.cg.shared.global [%0], [%1], 16;"
                 :: "r"(smem_addr), "l"(gptr));
}
__device__ __forceinline__ void cp_commit() {
    asm volatile("cp.async.commit_group;");
}

// packed fp32x2 (two exact fp32 FMAs per instruction; B300 FFMA2)
__device__ __forceinline__ unsigned long long ffma2(unsigned long long a,
                                                    unsigned long long b,
                                                    unsigned long long c) {
    unsigned long long d;
    asm("fma.rn.f32x2 %0, %1, %2, %3;" : "=l"(d) : "l"(a), "l"(b), "l"(c));
    return d;
}
__device__ __forceinline__ unsigned long long fmul2(unsigned long long a,
                                                    unsigned long long b) {
    unsigned long long d;
    asm("mul.rn.f32x2 %0, %1, %2;" : "=l"(d) : "l"(a), "l"(b));
    return d;
}
__device__ __forceinline__ unsigned long long pack2(float x) {
    unsigned long long r;
    uint32_t u = __float_as_uint(x);
    asm("mov.b64 %0, {%1, %1};" : "=l"(r) : "r"(u));
    return r;
}
__device__ __forceinline__ void unpack2(unsigned long long v, float& lo, float& hi) {
    uint32_t a, b;
    asm("mov.b64 {%0, %1}, %2;" : "=r"(a), "=r"(b) : "l"(v));
    lo = __uint_as_float(a); hi = __uint_as_float(b);
}

// ---------------- fp16x2 3-term tensor-core GEMM ---------------------------
#define BM   128
#define BN   64
#define BK   32
#define PADH 40                                  // halfs per smem row
#define SA_HI 0
#define SA_LO (BM * PADH)                        // 5120
#define SB_HI (2 * BM * PADH)                    // 10240
#define SB_LO (2 * BM * PADH + BN * PADH)        // 12800
#define STAGE_H (2 * BM * PADH + 2 * BN * PADH)  // 15360 halfs
#define GEMM_SMEM (2 * STAGE_H * 2)              // 61440 B

__global__ void __launch_bounds__(256, 3)
gemm16(const __half* __restrict__ Ah, const __half* __restrict__ Al,
       const __half* __restrict__ Bh, const __half* __restrict__ Bl,
       const float* __restrict__ bias, float* __restrict__ C,
       __half* __restrict__ Ch, __half* __restrict__ Cl,
       int K, int N, int relu)
{
    extern __shared__ __half sh[];
    const uint32_t smb = (uint32_t)__cvta_generic_to_shared(sh);

    const int tid  = threadIdx.x;
    const int warp = tid >> 5;
    const int lane = tid & 31;
    const int wm   = warp >> 1;
    const int wn   = warp & 1;
    const int gid  = lane >> 2;
    const int qid  = lane & 3;
    const int m0   = blockIdx.y * BM;
    const int n0   = blockIdx.x * BN;
    const int NC   = K >> 5;

    const int lm = lane >> 3;
    const int l7 = lane & 7;
    int arow[2];
#pragma unroll
    for (int tm = 0; tm < 2; tm++)
        arow[tm] = (wm * 32 + tm * 16 + (lm & 1) * 8 + l7) * PADH + (lm >> 1) * 8;
    int brow[4];
#pragma unroll
    for (int tn = 0; tn < 4; tn++)
        brow[tn] = (wn * 32 + tn * 8 + l7) * PADH + (lm & 1) * 8;

    float acc[2][4][4];
#pragma unroll
    for (int i = 0; i < 2; i++)
#pragma unroll
        for (int j = 0; j < 4; j++)
#pragma unroll
            for (int t = 0; t < 4; t++) acc[i][j][t] = 0.f;

    const int ar = tid >> 1;
    const int aq = (tid & 1) * 2;
    const int br2 = tid >> 2;
    const int bq = tid & 3;

    auto load_stage = [&](int c, int s) {
        const int k0 = c * BK;
        uint32_t st = smb + (uint32_t)(s * STAGE_H) * 2;
#pragma unroll
        for (int i = 0; i < 2; i++) {
            int q = aq + i;
            cp_async16(st + (uint32_t)(SA_HI + ar * PADH + q * 8) * 2,
                       Ah + (size_t)(m0 + ar) * K + k0 + q * 8);
            cp_async16(st + (uint32_t)(SA_LO + ar * PADH + q * 8) * 2,
                       Al + (size_t)(m0 + ar) * K + k0 + q * 8);
        }
        cp_async16(st + (uint32_t)(SB_HI + br2 * PADH + bq * 8) * 2,
                   Bh + (size_t)(n0 + br2) * K + k0 + bq * 8);
        cp_async16(st + (uint32_t)(SB_LO + br2 * PADH + bq * 8) * 2,
                   Bl + (size_t)(n0 + br2) * K + k0 + bq * 8);
        cp_commit();
    };

    load_stage(0, 0);
    if (NC > 1) load_stage(1, 1);

    for (int c = 0; c < NC; c++) {
        if (c + 1 < NC) asm volatile("cp.async.wait_group 1;" ::: "memory");
        else            asm volatile("cp.async.wait_group 0;" ::: "memory");
        __syncthreads();

        const uint32_t sbase = smb + (uint32_t)((c & 1) * STAGE_H) * 2;

#pragma unroll
        for (int kk = 0; kk < 2; kk++) {
            const int kb = kk * 16;
            uint32_t ah[2][4], al[2][4];
#pragma unroll
            for (int tm = 0; tm < 2; tm++) {
                ldm_x4(ah[tm], sbase + (uint32_t)(SA_HI + arow[tm] + kb) * 2);
                ldm_x4(al[tm], sbase + (uint32_t)(SA_LO + arow[tm] + kb) * 2);
            }
#pragma unroll
            for (int tn = 0; tn < 4; tn++) {
                uint32_t bh[2], bl[2];
                ldm_x2(bh, sbase + (uint32_t)(SB_HI + brow[tn] + kb) * 2);
                ldm_x2(bl, sbase + (uint32_t)(SB_LO + brow[tn] + kb) * 2);
#pragma unroll
                for (int tm = 0; tm < 2; tm++) {
                    mma16(acc[tm][tn], ah[tm], bh);   // hh
                    mma16(acc[tm][tn], ah[tm], bl);   // hl
                    mma16(acc[tm][tn], al[tm], bh);   // lh
                }
            }
        }

        if (c + 2 < NC) {
            __syncthreads();
            load_stage(c + 2, c & 1);
        }
    }

    // ---- epilogue ----
#pragma unroll
    for (int tm = 0; tm < 2; tm++) {
#pragma unroll
        for (int tn = 0; tn < 4; tn++) {
            const float* d = acc[tm][tn];
            int row = m0 + wm * 32 + tm * 16 + gid;
            int col = n0 + wn * 32 + tn * 8 + 2 * qid;
            float bx = bias[col], by = bias[col + 1];
            float2 v0 = make_float2(d[0] + bx, d[1] + by);
            float2 v1 = make_float2(d[2] + bx, d[3] + by);
            if (relu) {
                v0.x = fmaxf(v0.x, 0.f); v0.y = fmaxf(v0.y, 0.f);
                v1.x = fmaxf(v1.x, 0.f); v1.y = fmaxf(v1.y, 0.f);
            }
            if (C) {
                *(float2*)(C + (size_t)row * N + col) = v0;
                *(float2*)(C + (size_t)(row + 8) * N + col) = v1;
            }
            if (Ch) {
                __half h0 = __float2half_rn(v0.x), h1 = __float2half_rn(v0.y);
                __half h2 = __float2half_rn(v1.x), h3 = __float2half_rn(v1.y);
                *(__half2*)(Ch + (size_t)row * N + col) = __halves2half2(h0, h1);
                *(__half2*)(Ch + (size_t)(row + 8) * N + col) = __halves2half2(h2, h3);
                __half l0 = __float2half_rn(v0.x - __half2float(h0));
                __half l1 = __float2half_rn(v0.y - __half2float(h1));
                __half l2 = __float2half_rn(v1.x - __half2float(h2));
                __half l3 = __float2half_rn(v1.y - __half2float(h3));
                *(__half2*)(Cl + (size_t)row * N + col) = __halves2half2(l0, l1);
                *(__half2*)(Cl + (size_t)(row + 8) * N + col) = __halves2half2(l2, l3);
            }
        }
    }
}

// ---------------- fp32 -> fp16 hi/lo converters ----------------------------
__global__ void conv_split(const float* __restrict__ src, __half* __restrict__ hi,
                           __half* __restrict__ lo, int n)
{
    int i = blockIdx.x * blockDim.x + threadIdx.x;
    if (i < n) {
        float v = src[i];
        __half h = __float2half_rn(v);
        hi[i] = h;
        lo[i] = __float2half_rn(v - __half2float(h));
    }
}

// all five weight tensors in ONE launch (keeps ncu -s 5 slot on a gemm)
__global__ void conv_weights(const float* __restrict__ emb_w,
                             const float* __restrict__ qkv_w,
                             const float* __restrict__ out_w,
                             const float* __restrict__ ff1_w,
                             const float* __restrict__ ff2_w,
                             __half* __restrict__ wh, __half* __restrict__ wl)
{
    int i = blockIdx.x * blockDim.x + threadIdx.x;
    if (i >= W_TOT) return;
    float v;
    if      (i < W_QKV) v = emb_w[i - W_EMB];
    else if (i < W_OUT) v = qkv_w[i - W_QKV];
    else if (i < W_FF1) v = out_w[i - W_OUT];
    else if (i < W_FF2) v = ff1_w[i - W_FF1];
    else                v = ff2_w[i - W_FF2];
    __half h = __float2half_rn(v);
    wh[i] = h;
    wl[i] = __float2half_rn(v - __half2float(h));
}

// ---------------- flash-style attention (f32x2 packed, exact fp32) ---------
__global__ void __launch_bounds__(128) attn_kernel(const float* __restrict__ qkv,
                                                   float* __restrict__ out,
                                                   __half* __restrict__ o16h,
                                                   __half* __restrict__ o16l)
{
    __shared__ float Ks[64][32];
    __shared__ float Vs[64][32];

    const int g  = blockIdx.x >> 3;
    const int h  = blockIdx.x & 7;
    const int tid = threadIdx.x;
    const int qi = blockIdx.y * 128 + tid;
    const int hc = h * HD;
    const float* base = qkv + (size_t)g * NN * (3 * E);

    unsigned long long q2[16];
    {
        const unsigned long long* qp =
            (const unsigned long long*)(base + (size_t)qi * (3 * E) + hc);
#pragma unroll
        for (int d = 0; d < 16; d++) q2[d] = qp[d];
    }

    unsigned long long acc2[16];
#pragma unroll
    for (int d = 0; d < 16; d++) acc2[d] = 0ULL;
    float mval = -1e30f, l = 0.f;
    const float scale = 0.17677669529663687f;    // 1/sqrt(32)

#pragma unroll 1
    for (int kt = 0; kt < NN; kt += 64) {
        const int row  = tid >> 1;
        const int half = (tid & 1) * 16;
        const float* kp = base + (size_t)(kt + row) * (3 * E) + E + hc + half;
        const float* vp = base + (size_t)(kt + row) * (3 * E) + 2 * E + hc + half;
#pragma unroll
        for (int c = 0; c < 16; c += 4) {
            *(float4*)&Ks[row][half + c] = *(const float4*)(kp + c);
            *(float4*)&Vs[row][half + c] = *(const float4*)(vp + c);
        }
        __syncthreads();

#pragma unroll 1
        for (int jc = 0; jc < 64; jc += 16) {
            float s[16];
            float cmax = -1e30f;
#pragma unroll
            for (int j = 0; j < 16; j++) {
                const unsigned long long* krow = (const unsigned long long*)&Ks[jc + j][0];
                unsigned long long s2 = 0ULL;
#pragma unroll
                for (int d = 0; d < 16; d++) s2 = ffma2(q2[d], krow[d], s2);
                float a, b; unpack2(s2, a, b);
                float sv = (a + b) * scale;
                s[j] = sv;
                cmax = fmaxf(cmax, sv);
            }
            float mnew = fmaxf(mval, cmax);
            float corr = __expf(mval - mnew);
            l *= corr;
            unsigned long long corr2 = pack2(corr);
#pragma unroll
            for (int d = 0; d < 16; d++) acc2[d] = fmul2(acc2[d], corr2);
#pragma unroll
            for (int j = 0; j < 16; j++) {
                float p = __expf(s[j] - mnew);
                l += p;
                unsigned long long p2 = pack2(p);
                const unsigned long long* vrow = (const unsigned long long*)&Vs[jc + j][0];
#pragma unroll
                for (int d = 0; d < 16; d++) acc2[d] = ffma2(p2, vrow[d], acc2[d]);
            }
            mval = mnew;
        }
        __syncthreads();
    }

    float inv = 1.f / l;
    const size_t ob = (size_t)(g * NN + qi) * E + hc;
#pragma unroll
    for (int d = 0; d < 16; d++) {
        float a, b; unpack2(acc2[d], a, b);
        float v0 = a * inv, v1 = b * inv;
        out[ob + 2 * d]     = v0;
        out[ob + 2 * d + 1] = v1;
        __half h0 = __float2half_rn(v0), h1 = __float2half_rn(v1);
        *(__half2*)(o16h + ob + 2 * d) = __halves2half2(h0, h1);
        __half l0 = __float2half_rn(v0 - __half2float(h0));
        __half l1 = __float2half_rn(v1 - __half2float(h1));
        *(__half2*)(o16l + ob + 2 * d) = __halves2half2(l0, l1);
    }
}

// ---------------- fused residual + LayerNorm (+ fp16 split) ----------------
__global__ void ln_kernel(float* __restrict__ h, const float* __restrict__ add,
                          const float* __restrict__ w, const float* __restrict__ b,
                          __half* __restrict__ h16h, __half* __restrict__ h16l)
{
    __shared__ float red[256];
    const int r = blockIdx.x;
    const int t = threadIdx.x;
    const size_t off = (size_t)r * E + t;
    float x = h[off] + add[off];

    red[t] = x;
    __syncthreads();
#pragma unroll
    for (int s = 128; s > 0; s >>= 1) {
        if (t < s) red[t] += red[t + s];
        __syncthreads();
    }
    float mu = red[0] * (1.f / E);
    __syncthreads();

    float d = x - mu;
    red[t] = d * d;
    __syncthreads();
#pragma unroll
    for (int s = 128; s > 0; s >>= 1) {
        if (t < s) red[t] += red[t + s];
        __syncthreads();
    }
    float var = red[0] * (1.f / E);
    float y = d * rsqrtf(var + 1e-5f) * w[t] + b[t];
    h[off] = y;
    __half hh = __float2half_rn(y);
    h16h[off] = hh;
    h16l[off] = __float2half_rn(y - __half2float(hh));
}

// ---------------- score + sigmoid ------------------------------------------
__global__ void score_kernel(const float* __restrict__ h, const float* __restrict__ sw,
                             const float* __restrict__ sb, float* __restrict__ probs)
{
    const int warp = (blockIdx.x * blockDim.x + threadIdx.x) >> 5;
    const int lane = threadIdx.x & 31;
    if (warp >= GN) return;
    const float* hp = h + (size_t)warp * E;
    float s = 0.f;
#pragma unroll
    for (int k = 0; k < 8; k++) s = fmaf(hp[lane + k * 32], sw[lane + k * 32], s);
#pragma unroll
    for (int o = 16; o; o >>= 1) s += __shfl_xor_sync(0xffffffff, s, o);
    if (lane == 0) {
        s += sb[0];
        probs[warp] = 1.f / (1.f + expf(-s));
    }
}

// ---------------- per-graph top-k ------------------------------------------
__global__ void topk_kernel(const float* __restrict__ probs,
                            float* __restrict__ out, float* __restrict__ pf_buf)
{
    __shared__ unsigned long long keys[NN];
    __shared__ int sidx[KSEL];
    __shared__ int flags[NN];

    const int g = blockIdx.x;
    const int t = threadIdx.x;
    const float p = probs[g * NN + t];

    unsigned int fb = __float_as_uint(p);
    keys[t] = ((unsigned long long)fb << 32) | (unsigned)(NN - 1 - t);
    __syncthreads();

    for (int k = 2; k <= NN; k <<= 1) {
        for (int j = k >> 1; j > 0; j >>= 1) {
            int ixj = t ^ j;
            if (ixj > t) {
                unsigned long long a = keys[t], b = keys[ixj];
                bool up = ((t & k) == 0);
                if (up ? (a < b) : (a > b)) { keys[t] = b; keys[ixj] = a; }
            }
            __syncthreads();
        }
    }

    if (t < KSEL) sidx[t] = NN - 1 - (int)(unsigned)(keys[t] & 0xFFFFFFFFu);
    __syncthreads();

    for (int k = 2; k <= KSEL; k <<= 1) {
        for (int j = k >> 1; j > 0; j >>= 1) {
            int ixj = t ^ j;
            if (t < KSEL && ixj > t && ixj < KSEL) {
                int a = sidx[t], b = sidx[ixj];
                bool up = ((t & k) == 0);
                if (up ? (a > b) : (a < b)) { sidx[t] = b; sidx[ixj] = a; }
            }
            __syncthreads();
        }
    }

    flags[t] = 0;
    __syncthreads();
    if (t < KSEL) flags[sidx[t]] = 1;
    __syncthreads();

    if (t < KSEL)
        out[OFF_SAMP + g * KSEL + t] = (float)(g * NN + sidx[t]);

    float mask = (float)flags[t];
    float ind  = (mask - p) + p;
    float pf   = p * ind;
    pf_buf[g * NN + t] = pf;
    out[OFF_PF + g * NN + t] = pf;
}

// ---------------- edge weights ---------------------------------------------
__global__ void ew_kernel(const int* __restrict__ ei, const float* __restrict__ w,
                          const float* __restrict__ pf, float* __restrict__ out)
{
    int e = blockIdx.x * blockDim.x + threadIdx.x;
    if (e < NE_EDGE) {
        int s = ei[e];
        int d = ei[NE_EDGE + e];
        out[e] = w[e] * pf[s] * pf[d];
    }
}

// ---------------------------------------------------------------------------
extern "C" void kernel_launch(void* const* d_in, const int* in_sizes, int n_in,
                              void* d_out, int out_size)
{
    const float* x      = (const float*)d_in[0];
    const int*   ei     = (const int*)  d_in[1];
    const float* ew     = (const float*)d_in[2];
    const float* emb_w  = (const float*)d_in[3];
    const float* emb_b  = (const float*)d_in[4];
    const float* qkv_w  = (const float*)d_in[5];
    const float* qkv_b  = (const float*)d_in[6];
    const float* out_w  = (const float*)d_in[7];
    const float* out_b  = (const float*)d_in[8];
    const float* ln1_w  = (const float*)d_in[9];
    const float* ln1_b  = (const float*)d_in[10];
    const float* ln2_w  = (const float*)d_in[11];
    const float* ln2_b  = (const float*)d_in[12];
    const float* ff1_w  = (const float*)d_in[13];
    const float* ff1_b  = (const float*)d_in[14];
    const float* ff2_w  = (const float*)d_in[15];
    const float* ff2_b  = (const float*)d_in[16];
    const float* sc_w   = (const float*)d_in[17];
    const float* sc_b   = (const float*)d_in[18];
    float* out = (float*)d_out;

    float *h, *qkvb, *attn, *ff, *probs, *pf;
    cudaGetSymbolAddress((void**)&h,     g_h);
    cudaGetSymbolAddress((void**)&qkvb,  g_qkv);
    cudaGetSymbolAddress((void**)&attn,  g_attn);
    cudaGetSymbolAddress((void**)&ff,    g_ff);
    cudaGetSymbolAddress((void**)&probs, g_probs);
    cudaGetSymbolAddress((void**)&pf,    g_pf);

    __half *x16h, *x16l, *h16h, *h16l, *a16h, *a16l, *f16h, *f16l, *wh, *wl;
    cudaGetSymbolAddress((void**)&x16h, g_x16h);
    cudaGetSymbolAddress((void**)&x16l, g_x16l);
    cudaGetSymbolAddress((void**)&h16h, g_h16h);
    cudaGetSymbolAddress((void**)&h16l, g_h16l);
    cudaGetSymbolAddress((void**)&a16h, g_a16h);
    cudaGetSymbolAddress((void**)&a16l, g_a16l);
    cudaGetSymbolAddress((void**)&f16h, g_f16h);
    cudaGetSymbolAddress((void**)&f16l, g_f16l);
    cudaGetSymbolAddress((void**)&wh,   g_w16h);
    cudaGetSymbolAddress((void**)&wl,   g_w16l);

    cudaFuncSetAttribute(gemm16, cudaFuncAttributeMaxDynamicSharedMemorySize, GEMM_SMEM);

    // ---- converters: inputs (1 launch) + all weights (1 launch) ----
    {
        int n = GN * D_IN;
        conv_split<<<(n + 255) / 256, 256>>>(x, x16h, x16l, n);
        conv_weights<<<(W_TOT + 255) / 256, 256>>>(emb_w, qkv_w, out_w, ff1_w, ff2_w, wh, wl);
    }

    // embedding: x16 @ embw16 -> h f32 + h16 pair
    gemm16<<<dim3(E / BN, GN / BM), 256, GEMM_SMEM>>>(
        x16h, x16l, wh + W_EMB, wl + W_EMB, emb_b, h, h16h, h16l, D_IN, E, 0);

    for (int l = 0; l < NL; l++) {
        const __half* qwh = wh + W_QKV + (size_t)l * 3 * E * E;
        const __half* qwl = wl + W_QKV + (size_t)l * 3 * E * E;
        const __half* owh = wh + W_OUT + (size_t)l * E * E;
        const __half* owl = wl + W_OUT + (size_t)l * E * E;
        const __half* f1h = wh + W_FF1 + (size_t)l * DFF * E;
        const __half* f1l = wl + W_FF1 + (size_t)l * DFF * E;
        const __half* f2h = wh + W_FF2 + (size_t)l * E * DFF;
        const __half* f2l = wl + W_FF2 + (size_t)l * E * DFF;
        const float* qb  = qkv_b + (size_t)l * 3 * E;
        const float* ob  = out_b + (size_t)l * E;
        const float* f1b = ff1_b + (size_t)l * DFF;
        const float* f2b = ff2_b + (size_t)l * E;

        gemm16<<<dim3(3 * E / BN, GN / BM), 256, GEMM_SMEM>>>(
            h16h, h16l, qwh, qwl, qb, qkvb, ((__half*)0), ((__half*)0), E, 3 * E, 0);
        attn_kernel<<<dim3(NG * NH, NN / 128), 128>>>(qkvb, attn, a16h, a16l);
        gemm16<<<dim3(E / BN, GN / BM), 256, GEMM_SMEM>>>(
            a16h, a16l, owh, owl, ob, ff, ((__half*)0), ((__half*)0), E, E, 0);
        ln_kernel<<<GN, E>>>(h, ff, ln1_w + (size_t)l * E, ln1_b + (size_t)l * E, h16h, h16l);
        gemm16<<<dim3(DFF / BN, GN / BM), 256, GEMM_SMEM>>>(
            h16h, h16l, f1h, f1l, f1b, (float*)0, f16h, f16l, E, DFF, 1);
        gemm16<<<dim3(E / BN, GN / BM), 256, GEMM_SMEM>>>(
            f16h, f16l, f2h, f2l, f2b, attn, ((__half*)0), ((__half*)0), DFF, E, 0);
        ln_kernel<<<GN, E>>>(h, attn, ln2_w + (size_t)l * E, ln2_b + (size_t)l * E, h16h, h16l);
    }

    score_kernel<<<(GN * 32 + 255) / 256, 256>>>(h, sc_w, sc_b, probs);
    topk_kernel<<<NG, NN>>>(probs, out, pf);
    ew_kernel<<<(NE_EDGE + 255) / 256, 256>>>(ei, ew, pf, out);
}